// round 11
// baseline (speedup 1.0000x reference)
#include <cuda_runtime.h>
#include <stdint.h>
#include <math.h>

#define BQ 256
#define TQ 128
#define DETERQ 512
#define HIDQ 512
#define TOTQ 1024
#define OBSQ 768
#define ACTQ 7
#define FEATQ 3584
#define NBLK 128
#define NTHR 256

typedef unsigned long long ull;

__device__ float g_post_obs[(size_t)BQ * TQ * HIDQ];
__device__ float g_deter[2][BQ * DETERQ];
__device__ float g_h[BQ * 2 * HIDQ];
__device__ int   g_idx[BQ * 32];
__device__ uint2 g_keys[TQ];
__device__ unsigned g_cnt;
__device__ volatile unsigned g_gen;

// ---------- packed f32x2 ----------
__device__ __forceinline__ ull pack2(float x, float y) {
    ull r; asm("mov.b64 %0, {%1, %2};" : "=l"(r) : "f"(x), "f"(y)); return r;
}
__device__ __forceinline__ void fma2(ull& d, ull a, ull b) {
    asm("fma.rn.f32x2 %0, %1, %2, %0;" : "+l"(d) : "l"(a), "l"(b));
}
__device__ __forceinline__ float2 unpack2(ull v) {
    float lo, hi; asm("mov.b64 {%0, %1}, %2;" : "=f"(lo), "=f"(hi) : "l"(v));
    return make_float2(lo, hi);
}

// ---------- threefry (JAX-exact) ----------
__device__ __forceinline__ uint32_t rotl32(uint32_t x, int d) {
    return (x << d) | (x >> (32 - d));
}
__device__ __forceinline__ void tf4(uint32_t& x0, uint32_t& x1,
                                    int r0, int r1, int r2, int r3) {
    x0 += x1; x1 = rotl32(x1, r0); x1 ^= x0;
    x0 += x1; x1 = rotl32(x1, r1); x1 ^= x0;
    x0 += x1; x1 = rotl32(x1, r2); x1 ^= x0;
    x0 += x1; x1 = rotl32(x1, r3); x1 ^= x0;
}
__device__ __forceinline__ void threefry2x32(uint32_t k0, uint32_t k1,
                                             uint32_t c0, uint32_t c1,
                                             uint32_t& o0, uint32_t& o1) {
    uint32_t ks2 = k0 ^ k1 ^ 0x1BD11BDAu;
    uint32_t x0 = c0 + k0, x1 = c1 + k1;
    tf4(x0, x1, 13, 15, 26, 6);  x0 += k1;  x1 += ks2 + 1u;
    tf4(x0, x1, 17, 29, 16, 24); x0 += ks2; x1 += k0 + 2u;
    tf4(x0, x1, 13, 15, 26, 6);  x0 += k0;  x1 += k1 + 3u;
    tf4(x0, x1, 17, 29, 16, 24); x0 += k1;  x1 += ks2 + 4u;
    tf4(x0, x1, 13, 15, 26, 6);  x0 += ks2; x1 += k0 + 5u;
    o0 = x0; o1 = x1;
}
__device__ __forceinline__ float gumbel_of(uint2 key, uint32_t e) {
    uint32_t o0, o1;
    threefry2x32(key.x, key.y, 0u, e, o0, o1);
    uint32_t bits = o0 ^ o1;
    float f = __uint_as_float((bits >> 9) | 0x3f800000u) - 1.0f;
    float u = fmaxf(1.17549435e-38f, f);
    return -logf(-logf(u));
}

__global__ void init_kernel() {
    int i = blockIdx.x * 256 + threadIdx.x;
    if (i < BQ * DETERQ) g_deter[0][i] = 0.0f;
    if (blockIdx.x == 0 && threadIdx.x < TQ) {
        uint32_t t = threadIdx.x, o0, o1;
        threefry2x32(0u, 42u, 0u, t, o0, o1);
        g_keys[t] = make_uint2(o0, o1);
    }
}

// ---------- hoisted obs GEMM (proven bit-exact, unchanged) ----------
__global__ __launch_bounds__(256) void obs_gemm_kernel(const float* __restrict__ A,
                                                       const float* __restrict__ B,
                                                       float* __restrict__ C) {
    __shared__ __align__(16) float As[2][8][132];
    __shared__ __align__(16) float Bs[2][8][128];
    int bm = blockIdx.y * 128, bn = blockIdx.x * 128;
    int tid = threadIdx.x, tx = tid & 15, ty = tid >> 4;
    int arow = tid >> 1, ak = (tid & 1) * 4;
    int bk = tid >> 5, bn4 = (tid & 31) * 4;
    const float* aptr = A + (size_t)(bm + arow) * OBSQ + ak;
    const float* bptr = B + (size_t)bk * 512 + bn + bn4;
    float acc[8][8];
#pragma unroll
    for (int i = 0; i < 8; i++)
#pragma unroll
        for (int j = 0; j < 8; j++) acc[i][j] = 0.0f;
    float4 av = *(const float4*)aptr;
    float4 bv = *(const float4*)bptr;
    As[0][ak + 0][arow] = av.x; As[0][ak + 1][arow] = av.y;
    As[0][ak + 2][arow] = av.z; As[0][ak + 3][arow] = av.w;
    *(float4*)&Bs[0][bk][bn4] = bv;
    __syncthreads();
    const int NT = OBSQ / 8;
    for (int kt = 0; kt < NT; kt++) {
        int cur = kt & 1;
        if (kt + 1 < NT) {
            av = *(const float4*)(aptr + (kt + 1) * 8);
            bv = *(const float4*)(bptr + (size_t)(kt + 1) * 8 * 512);
        }
#pragma unroll
        for (int kk = 0; kk < 8; kk++) {
            float4 a0 = *(const float4*)&As[cur][kk][ty * 8];
            float4 a1 = *(const float4*)&As[cur][kk][ty * 8 + 4];
            float4 b0 = *(const float4*)&Bs[cur][kk][tx * 8];
            float4 b1 = *(const float4*)&Bs[cur][kk][tx * 8 + 4];
            float a[8] = {a0.x, a0.y, a0.z, a0.w, a1.x, a1.y, a1.z, a1.w};
            float b[8] = {b0.x, b0.y, b0.z, b0.w, b1.x, b1.y, b1.z, b1.w};
#pragma unroll
            for (int i = 0; i < 8; i++)
#pragma unroll
                for (int j = 0; j < 8; j++) acc[i][j] += a[i] * b[j];
        }
        if (kt + 1 < NT) {
            int nxt = cur ^ 1;
            As[nxt][ak + 0][arow] = av.x; As[nxt][ak + 1][arow] = av.y;
            As[nxt][ak + 2][arow] = av.z; As[nxt][ak + 3][arow] = av.w;
            *(float4*)&Bs[nxt][bk][bn4] = bv;
            __syncthreads();
        }
    }
#pragma unroll
    for (int i = 0; i < 8; i++) {
        size_t row = (size_t)(bm + ty * 8 + i);
        *(float4*)(C + row * 512 + bn + tx * 8) =
            make_float4(acc[i][0], acc[i][1], acc[i][2], acc[i][3]);
        *(float4*)(C + row * 512 + bn + tx * 8 + 4) =
            make_float4(acc[i][4], acc[i][5], acc[i][6], acc[i][7]);
    }
}

// ---------- grid barrier ----------
__device__ __forceinline__ void gsync() {
    __syncthreads();
    __threadfence();
    if (threadIdx.x == 0) {
        unsigned g = g_gen;
        if (atomicAdd(&g_cnt, 1u) == NBLK - 1u) {
            atomicExch(&g_cnt, 0u);
            __threadfence();
            g_gen = g + 1u;
        } else {
            while (g_gen == g) __nanosleep(64);
        }
    }
    __syncthreads();
}

// ---------- shared memory union ----------
struct SA {
    ull Asd[2][16][16];
    ull Bsd[2][16][96];
    float wact[ACTQ][192];
    float act[16][ACTQ];
    int idx[16][32];
};
struct SB { ull Asd[2][16][16]; ull Bsd[2][16][64]; };
struct SC { ull Asd[2][16][32]; ull Bsd[2][16][64]; };
union USmem { SA a; SB b; SC c; };

// ---------- Stage A: gh GEMM + gather-gi + GRU ----------
__device__ void stageA(USmem& u, int bid, int tid,
    const float* __restrict__ dprev, float* __restrict__ dnext,
    const float* __restrict__ w_hh, const float* __restrict__ b_hh,
    const float* __restrict__ w_ih, const float* __restrict__ b_ih,
    const float* __restrict__ actions, float* __restrict__ out, int t)
{
    SA& s = u.a;
    int bm = (bid >> 3) * 16, d0 = (bid & 7) * 64;
    int tx = tid & 31, ty = tid >> 5;

    for (int i = tid; i < ACTQ * 192; i += NTHR) {
        int r = i / 192, c = i % 192;
        s.wact[r][c] = w_ih[(size_t)(TOTQ + r) * 1536 + (c >> 6) * 512 + d0 + (c & 63)];
    }
    for (int i = tid; i < 16 * ACTQ; i += NTHR) {
        int b = i / ACTQ, j = i % ACTQ;
        s.act[b][j] = actions[((size_t)(bm + b) * TQ + t) * ACTQ + j];
    }
    if (t > 0) s.idx[tid >> 5][tid & 31] =
        __ldcg(&g_idx[(bm + (tid >> 5)) * 32 + (tid & 31)]);
    if (t > 0 && tid < NTHR) {
        int i = tid + NTHR;
        if (i < 512) s.idx[i >> 5][i & 31] =
            __ldcg(&g_idx[(bm + (i >> 5)) * 32 + (i & 31)]);
    }

    int lak = tid & 15, lar = tid >> 4;
    const float* aptr = dprev + (size_t)(bm + lar) * DETERQ + lak;
    int bkk[3], bqq[3];
    const float* bptr[3];
#pragma unroll
    for (int j = 0; j < 3; j++) {
        int i = tid + j * NTHR;            // 0..767 float4 slots
        bkk[j] = i / 48;
        bqq[j] = i % 48;                   // ulonglong2 slot in row
        int c = bqq[j] * 4;
        bptr[j] = w_hh + (size_t)bkk[j] * 1536 + (c >> 6) * 512 + d0 + (c & 63);
    }

    float an = __ldcg(aptr);
    float4 bn0 = *(const float4*)bptr[0];
    float4 bn1 = *(const float4*)bptr[1];
    float4 bn2 = *(const float4*)bptr[2];
    s.Asd[0][lak][lar] = pack2(an, an);
    *(float4*)&s.Bsd[0][bkk[0]][bqq[0] * 2] = bn0;
    *(float4*)&s.Bsd[0][bkk[1]][bqq[1] * 2] = bn1;
    *(float4*)&s.Bsd[0][bkk[2]][bqq[2] * 2] = bn2;
    __syncthreads();

    ull acc[2][3];
#pragma unroll
    for (int i = 0; i < 2; i++)
#pragma unroll
        for (int g = 0; g < 3; g++) acc[i][g] = 0ull;

    const int NT = DETERQ / 16;
    for (int kc = 0; kc < NT; kc++) {
        int cur = kc & 1;
        if (kc + 1 < NT) {
            an  = __ldcg(aptr + (kc + 1) * 16);
            bn0 = *(const float4*)(bptr[0] + (size_t)(kc + 1) * 16 * 1536);
            bn1 = *(const float4*)(bptr[1] + (size_t)(kc + 1) * 16 * 1536);
            bn2 = *(const float4*)(bptr[2] + (size_t)(kc + 1) * 16 * 1536);
        }
#pragma unroll
        for (int kk = 0; kk < 16; kk++) {
            ulonglong2 a01 = *(const ulonglong2*)&s.Asd[cur][kk][ty * 2];
            ull b0 = s.Bsd[cur][kk][tx];
            ull b1 = s.Bsd[cur][kk][32 + tx];
            ull b2 = s.Bsd[cur][kk][64 + tx];
            fma2(acc[0][0], a01.x, b0); fma2(acc[0][1], a01.x, b1); fma2(acc[0][2], a01.x, b2);
            fma2(acc[1][0], a01.y, b0); fma2(acc[1][1], a01.y, b1); fma2(acc[1][2], a01.y, b2);
        }
        if (kc + 1 < NT) {
            int nxt = cur ^ 1;
            s.Asd[nxt][lak][lar] = pack2(an, an);
            *(float4*)&s.Bsd[nxt][bkk[0]][bqq[0] * 2] = bn0;
            *(float4*)&s.Bsd[nxt][bkk[1]][bqq[1] * 2] = bn1;
            *(float4*)&s.Bsd[nxt][bkk[2]][bqq[2] * 2] = bn2;
            __syncthreads();
        }
    }

    int d = d0 + tx * 2;
#pragma unroll
    for (int i = 0; i < 2; i++) {
        int row = bm + ty * 2 + i;
        float gi[3][2];
#pragma unroll
        for (int g = 0; g < 3; g++) {
            gi[g][0] = b_ih[g * DETERQ + d + 0];
            gi[g][1] = b_ih[g * DETERQ + d + 1];
        }
        if (t > 0) {
#pragma unroll 4
            for (int sc = 0; sc < 32; sc++) {
                const float* wr = w_ih + (size_t)(sc * 32 + s.idx[ty * 2 + i][sc]) * 1536 + d;
#pragma unroll
                for (int g = 0; g < 3; g++) {
                    gi[g][0] += wr[g * DETERQ + 0];
                    gi[g][1] += wr[g * DETERQ + 1];
                }
            }
        }
#pragma unroll
        for (int r = 0; r < ACTQ; r++) {
            float a = s.act[ty * 2 + i][r];
#pragma unroll
            for (int g = 0; g < 3; g++) {
                gi[g][0] += a * s.wact[r][g * 64 + tx * 2 + 0];
                gi[g][1] += a * s.wact[r][g * 64 + tx * 2 + 1];
            }
        }
        float2 hr = unpack2(acc[i][0]);
        float2 hz = unpack2(acc[i][1]);
        float2 hn = unpack2(acc[i][2]);
        float2 dnv;
#pragma unroll
        for (int j = 0; j < 2; j++) {
            float ghr = (j ? hr.y : hr.x) + b_hh[d + j];
            float ghz = (j ? hz.y : hz.x) + b_hh[DETERQ + d + j];
            float ghn = (j ? hn.y : hn.x) + b_hh[2 * DETERQ + d + j];
            float rr = 1.0f / (1.0f + expf(-(gi[0][j] + ghr)));
            float zz = 1.0f / (1.0f + expf(-(gi[1][j] + ghz)));
            float nn = tanhf(gi[2][j] + rr * ghn);
            float dp = __ldcg(dprev + (size_t)row * DETERQ + d + j);
            float dn = (1.0f - zz) * nn + zz * dp;
            if (j) dnv.y = dn; else dnv.x = dn;
        }
        *(float2*)(dnext + (size_t)row * DETERQ + d) = dnv;
        *(float2*)(out + ((size_t)row * TQ + t) * FEATQ + d) = dnv;
    }
}

// ---------- Stage B: hidden layers ----------
__device__ void stageB(USmem& u, int bid, int tid,
    const float* __restrict__ deter,
    const float* __restrict__ prior_w1, const float* __restrict__ prior_b1,
    const float* __restrict__ post_w1,  const float* __restrict__ post_b1,
    int t)
{
    SB& s = u.b;
    int bm = (bid >> 3) * 16, n0 = (bid & 7) * 128;
    bool post = (n0 >= HIDQ);
    int nc = post ? n0 - HIDQ : n0;
    const float* Bm = post ? post_w1 : prior_w1;
    const float* bias = post ? post_b1 : prior_b1;
    int tx = tid & 31, ty = tid >> 5;

    int lak = tid & 15, lar = tid >> 4;
    const float* aptr = deter + (size_t)(bm + lar) * DETERQ + lak;
    int bk0 = tid >> 5, bq0 = tid & 31;
    int bk1 = (tid + NTHR) >> 5, bq1 = (tid + NTHR) & 31;
    const float* bp0 = Bm + (size_t)bk0 * HIDQ + nc + bq0 * 4;
    const float* bp1 = Bm + (size_t)bk1 * HIDQ + nc + bq1 * 4;

    float an = __ldcg(aptr);
    float4 bn0 = *(const float4*)bp0;
    float4 bn1 = *(const float4*)bp1;
    s.Asd[0][lak][lar] = pack2(an, an);
    *(float4*)&s.Bsd[0][bk0][bq0 * 2] = bn0;
    *(float4*)&s.Bsd[0][bk1][bq1 * 2] = bn1;
    __syncthreads();

    ull acc[2][2];
    acc[0][0] = acc[0][1] = acc[1][0] = acc[1][1] = 0ull;

    const int NT = DETERQ / 16;
    for (int kc = 0; kc < NT; kc++) {
        int cur = kc & 1;
        if (kc + 1 < NT) {
            an  = __ldcg(aptr + (kc + 1) * 16);
            bn0 = *(const float4*)(bp0 + (size_t)(kc + 1) * 16 * HIDQ);
            bn1 = *(const float4*)(bp1 + (size_t)(kc + 1) * 16 * HIDQ);
        }
#pragma unroll
        for (int kk = 0; kk < 16; kk++) {
            ulonglong2 a01 = *(const ulonglong2*)&s.Asd[cur][kk][ty * 2];
            ulonglong2 bq = *(const ulonglong2*)&s.Bsd[cur][kk][tx * 2];
            fma2(acc[0][0], a01.x, bq.x); fma2(acc[0][1], a01.x, bq.y);
            fma2(acc[1][0], a01.y, bq.x); fma2(acc[1][1], a01.y, bq.y);
        }
        if (kc + 1 < NT) {
            int nxt = cur ^ 1;
            s.Asd[nxt][lak][lar] = pack2(an, an);
            *(float4*)&s.Bsd[nxt][bk0][bq0 * 2] = bn0;
            *(float4*)&s.Bsd[nxt][bk1][bq1 * 2] = bn1;
            __syncthreads();
        }
    }

#pragma unroll
    for (int i = 0; i < 2; i++) {
        int row = bm + ty * 2 + i;
        float2 p0 = unpack2(acc[i][0]);
        float2 p1 = unpack2(acc[i][1]);
        float v[4] = {p0.x, p0.y, p1.x, p1.y};
        float4 res;
#pragma unroll
        for (int j = 0; j < 4; j++) {
            int lc = nc + tx * 4 + j;
            float x = v[j] + bias[lc];
            if (post) x += g_post_obs[((size_t)row * TQ + t) * HIDQ + lc];
            x = (x > 0.0f) ? x : expm1f(x);
            ((float*)&res)[j] = x;
        }
        *(float4*)(g_h + (size_t)row * (2 * HIDQ) + n0 + tx * 4) = res;
    }
}

// ---------- Stage C: logits + sampler ----------
__device__ void stageC(USmem& u, int bid, int tid,
    const float* __restrict__ prior_w2, const float* __restrict__ prior_b2,
    const float* __restrict__ post_w2,  const float* __restrict__ post_b2,
    float* __restrict__ out, int t)
{
    SC& s = u.c;
    int bm = (bid >> 4) * 32, n0 = (bid & 15) * 128;
    bool post = (n0 >= TOTQ);
    int nc = post ? n0 - TOTQ : n0;
    const float* Bm = post ? post_w2 : prior_w2;
    const float* bias = post ? post_b2 : prior_b2;
    int aoff = post ? HIDQ : 0;
    int tx = tid & 31, ty = tid >> 5;

    int lak0 = tid & 15, lar0 = tid >> 4;
    int lak1 = (tid + NTHR) & 15, lar1 = (tid + NTHR) >> 4;
    const float* ap0 = g_h + (size_t)(bm + lar0) * (2 * HIDQ) + aoff + lak0;
    const float* ap1 = g_h + (size_t)(bm + lar1) * (2 * HIDQ) + aoff + lak1;
    int bk0 = tid >> 5, bq0 = tid & 31;
    int bk1 = (tid + NTHR) >> 5, bq1 = (tid + NTHR) & 31;
    const float* bp0 = Bm + (size_t)bk0 * TOTQ + nc + bq0 * 4;
    const float* bp1 = Bm + (size_t)bk1 * TOTQ + nc + bq1 * 4;

    float an0 = __ldcg(ap0), an1 = __ldcg(ap1);
    float4 bn0 = *(const float4*)bp0;
    float4 bn1 = *(const float4*)bp1;
    s.Asd[0][lak0][lar0] = pack2(an0, an0);
    s.Asd[0][lak1][lar1] = pack2(an1, an1);
    *(float4*)&s.Bsd[0][bk0][bq0 * 2] = bn0;
    *(float4*)&s.Bsd[0][bk1][bq1 * 2] = bn1;
    __syncthreads();

    ull acc[4][2];
#pragma unroll
    for (int i = 0; i < 4; i++) { acc[i][0] = 0ull; acc[i][1] = 0ull; }

    const int NT = HIDQ / 16;
    for (int kc = 0; kc < NT; kc++) {
        int cur = kc & 1;
        if (kc + 1 < NT) {
            an0 = __ldcg(ap0 + (kc + 1) * 16);
            an1 = __ldcg(ap1 + (kc + 1) * 16);
            bn0 = *(const float4*)(bp0 + (size_t)(kc + 1) * 16 * TOTQ);
            bn1 = *(const float4*)(bp1 + (size_t)(kc + 1) * 16 * TOTQ);
        }
#pragma unroll
        for (int kk = 0; kk < 16; kk++) {
            ulonglong2 a01 = *(const ulonglong2*)&s.Asd[cur][kk][ty * 4];
            ulonglong2 a23 = *(const ulonglong2*)&s.Asd[cur][kk][ty * 4 + 2];
            ulonglong2 bq = *(const ulonglong2*)&s.Bsd[cur][kk][tx * 2];
            fma2(acc[0][0], a01.x, bq.x); fma2(acc[0][1], a01.x, bq.y);
            fma2(acc[1][0], a01.y, bq.x); fma2(acc[1][1], a01.y, bq.y);
            fma2(acc[2][0], a23.x, bq.x); fma2(acc[2][1], a23.x, bq.y);
            fma2(acc[3][0], a23.y, bq.x); fma2(acc[3][1], a23.y, bq.y);
        }
        if (kc + 1 < NT) {
            int nxt = cur ^ 1;
            s.Asd[nxt][lak0][lar0] = pack2(an0, an0);
            s.Asd[nxt][lak1][lar1] = pack2(an1, an1);
            *(float4*)&s.Bsd[nxt][bk0][bq0 * 2] = bn0;
            *(float4*)&s.Bsd[nxt][bk1][bq1 * 2] = bn1;
            __syncthreads();
        }
    }

    float lv[4][4];
#pragma unroll
    for (int i = 0; i < 4; i++) {
        int row = bm + ty * 4 + i;
        float2 p0 = unpack2(acc[i][0]);
        float2 p1 = unpack2(acc[i][1]);
        lv[i][0] = p0.x + bias[nc + tx * 4 + 0];
        lv[i][1] = p0.y + bias[nc + tx * 4 + 1];
        lv[i][2] = p1.x + bias[nc + tx * 4 + 2];
        lv[i][3] = p1.y + bias[nc + tx * 4 + 3];
        *(float4*)(out + ((size_t)row * TQ + t) * FEATQ + 1536 + n0 + tx * 4) =
            make_float4(lv[i][0], lv[i][1], lv[i][2], lv[i][3]);
    }

    if (post) {
        int pc0 = nc + tx * 4;
        int sg = pc0 >> 5, cb = pc0 & 31;
        uint2 key = g_keys[t];
#pragma unroll
        for (int i = 0; i < 4; i++) {
            int row = bm + ty * 4 + i;
            float best = -__int_as_float(0x7f800000);
            int bidx = 0;
            uint32_t eb = (uint32_t)row * 1024u + (uint32_t)sg * 32u + (uint32_t)cb;
#pragma unroll
            for (int j = 0; j < 4; j++) {
                float val = lv[i][j] + gumbel_of(key, eb + (uint32_t)j);
                if (val > best) { best = val; bidx = cb + j; }
            }
#pragma unroll
            for (int off = 4; off > 0; off >>= 1) {
                float ov = __shfl_down_sync(0xffffffffu, best, off, 8);
                int   oi = __shfl_down_sync(0xffffffffu, bidx, off, 8);
                if (ov > best || (ov == best && oi < bidx)) { best = ov; bidx = oi; }
            }
            int win = __shfl_sync(0xffffffffu, bidx, 0, 8);
            *(float4*)(out + ((size_t)row * TQ + t) * FEATQ + 512 + sg * 32 + cb) =
                make_float4((cb + 0 == win) ? 1.0f : 0.0f,
                            (cb + 1 == win) ? 1.0f : 0.0f,
                            (cb + 2 == win) ? 1.0f : 0.0f,
                            (cb + 3 == win) ? 1.0f : 0.0f);
            if ((tid & 7) == 0) g_idx[row * 32 + sg] = win;
        }
    }
}

// ---------- persistent kernel ----------
__global__ __launch_bounds__(NTHR, 1) void rssm_kernel(
    const float* __restrict__ actions,
    const float* __restrict__ w_ih, const float* __restrict__ w_hh,
    const float* __restrict__ b_ih, const float* __restrict__ b_hh,
    const float* __restrict__ prior_w1, const float* __restrict__ prior_b1,
    const float* __restrict__ prior_w2, const float* __restrict__ prior_b2,
    const float* __restrict__ post_w1,  const float* __restrict__ post_b1,
    const float* __restrict__ post_w2,  const float* __restrict__ post_b2,
    float* __restrict__ out)
{
    __shared__ USmem u;
    int bid = blockIdx.x, tid = threadIdx.x;
    for (int t = 0; t < TQ; t++) {
        const float* dprev = g_deter[t & 1];
        float* dnext = g_deter[(t & 1) ^ 1];
        stageA(u, bid, tid, dprev, dnext, w_hh, b_hh, w_ih, b_ih, actions, out, t);
        gsync();
        stageB(u, bid, tid, dnext, prior_w1, prior_b1, post_w1, post_b1, t);
        gsync();
        stageC(u, bid, tid, prior_w2, prior_b2, post_w2, post_b2, out, t);
        gsync();
    }
}

extern "C" void kernel_launch(void* const* d_in, const int* in_sizes, int n_in,
                              void* d_out, int out_size) {
    (void)in_sizes; (void)n_in; (void)out_size;
    const float* obs      = (const float*)d_in[0];
    const float* actions  = (const float*)d_in[1];
    const float* w_ih     = (const float*)d_in[2];
    const float* w_hh     = (const float*)d_in[3];
    const float* b_ih     = (const float*)d_in[4];
    const float* b_hh     = (const float*)d_in[5];
    const float* prior_w1 = (const float*)d_in[6];
    const float* prior_b1 = (const float*)d_in[7];
    const float* prior_w2 = (const float*)d_in[8];
    const float* prior_b2 = (const float*)d_in[9];
    const float* post_w1  = (const float*)d_in[10];
    const float* post_b1  = (const float*)d_in[11];
    const float* post_w2  = (const float*)d_in[12];
    const float* post_b2  = (const float*)d_in[13];
    float* out = (float*)d_out;

    void* p_po;
    cudaGetSymbolAddress(&p_po, g_post_obs);

    init_kernel<<<512, 256>>>();
    obs_gemm_kernel<<<dim3(4, (BQ * TQ) / 128), 256>>>(
        obs, post_w1 + (size_t)DETERQ * HIDQ, (float*)p_po);
    rssm_kernel<<<NBLK, NTHR>>>(actions, w_ih, w_hh, b_ih, b_hh,
                                prior_w1, prior_b1, prior_w2, prior_b2,
                                post_w1, post_b1, post_w2, post_b2, out);
}

// round 12
// speedup vs baseline: 1.0198x; 1.0198x over previous
#include <cuda_runtime.h>
#include <stdint.h>
#include <math.h>

#define BQ 256
#define TQ 128
#define DETERQ 512
#define HIDQ 512
#define TOTQ 1024
#define OBSQ 768
#define ACTQ 7
#define FEATQ 3584

typedef unsigned long long ull;

// ---------------- device scratch ----------------
__device__ float g_post_obs[(size_t)BQ * TQ * HIDQ];
__device__ float g_gh[BQ * 3 * DETERQ];
__device__ float g_h[BQ * 2 * HIDQ];
__device__ float g_deter[BQ * DETERQ];
__device__ int   g_idx[BQ * 32];
__device__ uint2 g_keys[TQ];

// ---------------- packed f32x2 ----------------
__device__ __forceinline__ ull pack2(float x, float y) {
    ull r; asm("mov.b64 %0, {%1, %2};" : "=l"(r) : "f"(x), "f"(y)); return r;
}
__device__ __forceinline__ void fma2(ull& d, ull a, ull b) {
    asm("fma.rn.f32x2 %0, %1, %2, %0;" : "+l"(d) : "l"(a), "l"(b));
}
__device__ __forceinline__ float2 unpack2(ull v) {
    float lo, hi; asm("mov.b64 {%0, %1}, %2;" : "=f"(lo), "=f"(hi) : "l"(v));
    return make_float2(lo, hi);
}

// ---------------- threefry2x32 (JAX-exact) ----------------
__device__ __forceinline__ uint32_t rotl32(uint32_t x, int d) {
    return (x << d) | (x >> (32 - d));
}
__device__ __forceinline__ void tf4(uint32_t& x0, uint32_t& x1,
                                    int r0, int r1, int r2, int r3) {
    x0 += x1; x1 = rotl32(x1, r0); x1 ^= x0;
    x0 += x1; x1 = rotl32(x1, r1); x1 ^= x0;
    x0 += x1; x1 = rotl32(x1, r2); x1 ^= x0;
    x0 += x1; x1 = rotl32(x1, r3); x1 ^= x0;
}
__device__ __forceinline__ void threefry2x32(uint32_t k0, uint32_t k1,
                                             uint32_t c0, uint32_t c1,
                                             uint32_t& o0, uint32_t& o1) {
    uint32_t ks2 = k0 ^ k1 ^ 0x1BD11BDAu;
    uint32_t x0 = c0 + k0, x1 = c1 + k1;
    tf4(x0, x1, 13, 15, 26, 6);  x0 += k1;  x1 += ks2 + 1u;
    tf4(x0, x1, 17, 29, 16, 24); x0 += ks2; x1 += k0 + 2u;
    tf4(x0, x1, 13, 15, 26, 6);  x0 += k0;  x1 += k1 + 3u;
    tf4(x0, x1, 17, 29, 16, 24); x0 += k1;  x1 += ks2 + 4u;
    tf4(x0, x1, 13, 15, 26, 6);  x0 += ks2; x1 += k0 + 5u;
    o0 = x0; o1 = x1;
}
__device__ __forceinline__ float gumbel_of(uint2 key, uint32_t e) {
    uint32_t o0, o1;
    threefry2x32(key.x, key.y, 0u, e, o0, o1);
    uint32_t bits = o0 ^ o1;
    float f = __uint_as_float((bits >> 9) | 0x3f800000u) - 1.0f;
    float u = fmaxf(1.17549435e-38f, f);
    return -logf(-logf(u));
}

// ---------------- init ----------------
__global__ void init_kernel() {
    int i = blockIdx.x * 256 + threadIdx.x;
    if (i < BQ * DETERQ) g_deter[i] = 0.0f;
    if (blockIdx.x == 0 && threadIdx.x < TQ) {
        uint32_t t = threadIdx.x, o0, o1;
        threefry2x32(0u, 42u, 0u, t, o0, o1);
        g_keys[t] = make_uint2(o0, o1);
    }
}

// ---------------- hoisted obs GEMM (proven bit-exact, unchanged from R8/R11) ----------------
__global__ __launch_bounds__(256) void obs_gemm_kernel(const float* __restrict__ A,
                                                       const float* __restrict__ B,
                                                       float* __restrict__ C) {
    __shared__ __align__(16) float As[2][8][132];
    __shared__ __align__(16) float Bs[2][8][128];
    int bm = blockIdx.y * 128, bn = blockIdx.x * 128;
    int tid = threadIdx.x, tx = tid & 15, ty = tid >> 4;
    int arow = tid >> 1, ak = (tid & 1) * 4;
    int bk = tid >> 5, bn4 = (tid & 31) * 4;
    const float* aptr = A + (size_t)(bm + arow) * OBSQ + ak;
    const float* bptr = B + (size_t)bk * 512 + bn + bn4;
    float acc[8][8];
#pragma unroll
    for (int i = 0; i < 8; i++)
#pragma unroll
        for (int j = 0; j < 8; j++) acc[i][j] = 0.0f;
    float4 av = *(const float4*)aptr;
    float4 bv = *(const float4*)bptr;
    As[0][ak + 0][arow] = av.x; As[0][ak + 1][arow] = av.y;
    As[0][ak + 2][arow] = av.z; As[0][ak + 3][arow] = av.w;
    *(float4*)&Bs[0][bk][bn4] = bv;
    __syncthreads();
    const int NT = OBSQ / 8;
    for (int kt = 0; kt < NT; kt++) {
        int cur = kt & 1;
        if (kt + 1 < NT) {
            av = *(const float4*)(aptr + (kt + 1) * 8);
            bv = *(const float4*)(bptr + (size_t)(kt + 1) * 8 * 512);
        }
#pragma unroll
        for (int kk = 0; kk < 8; kk++) {
            float4 a0 = *(const float4*)&As[cur][kk][ty * 8];
            float4 a1 = *(const float4*)&As[cur][kk][ty * 8 + 4];
            float4 b0 = *(const float4*)&Bs[cur][kk][tx * 8];
            float4 b1 = *(const float4*)&Bs[cur][kk][tx * 8 + 4];
            float a[8] = {a0.x, a0.y, a0.z, a0.w, a1.x, a1.y, a1.z, a1.w};
            float b[8] = {b0.x, b0.y, b0.z, b0.w, b1.x, b1.y, b1.z, b1.w};
#pragma unroll
            for (int i = 0; i < 8; i++)
#pragma unroll
                for (int j = 0; j < 8; j++) acc[i][j] += a[i] * b[j];
        }
        if (kt + 1 < NT) {
            int nxt = cur ^ 1;
            As[nxt][ak + 0][arow] = av.x; As[nxt][ak + 1][arow] = av.y;
            As[nxt][ak + 2][arow] = av.z; As[nxt][ak + 3][arow] = av.w;
            *(float4*)&Bs[nxt][bk][bn4] = bv;
            __syncthreads();
        }
    }
#pragma unroll
    for (int i = 0; i < 8; i++) {
        size_t row = (size_t)(bm + ty * 8 + i);
        *(float4*)(C + row * 512 + bn + tx * 8) =
            make_float4(acc[i][0], acc[i][1], acc[i][2], acc[i][3]);
        *(float4*)(C + row * 512 + bn + tx * 8 + 4) =
            make_float4(acc[i][4], acc[i][5], acc[i][6], acc[i][7]);
    }
}

// ---------------- generic f32x2 GEMM, R2 geometry: 32x64 tile / 128 thr / 4x4 microtile ----
struct GemmP {
    const float* A; int lda; int acol2;
    const float* B1; const float* B2; int ldb;
    const float* bias1; const float* bias2;
    const float* extra2; long long ld_extra;
    float* C; long long ldc;
    int K, nsplit;
    int act;       // 0 none, 1 ELU
    int sample;    // gumbel argmax on second half
    int t;
    float* stoch; long long ld_st;
};

__global__ __launch_bounds__(128) void gemm_kernel(GemmP p) {
    // padded, 16B-aligned packed tiles
    __shared__ __align__(16) ull Asd[16][34];   // [k][row] as (a,a)
    __shared__ __align__(16) ull Bsd[16][34];   // [k][colpair]
    int bn = blockIdx.x * 64;
    int bm = blockIdx.y * 32;
    bool second = (bn >= p.nsplit);
    const float* B    = second ? p.B2 : p.B1;
    const float* bias = second ? p.bias2 : p.bias1;
    const float* A    = p.A + (second ? p.acol2 : 0);
    int bcol = second ? (bn - p.nsplit) : bn;

    int tid = threadIdx.x;
    int tx = tid & 15, ty = tid >> 4;

    ull acc[4][2];
#pragma unroll
    for (int i = 0; i < 4; i++) { acc[i][0] = 0ull; acc[i][1] = 0ull; }

    int arow = tid >> 2;            // 0..31
    int akq  = (tid & 3) << 2;      // 0,4,8,12
    int bk   = tid >> 4;            // 0..7
    int bnn  = (tid & 15) << 2;     // 0..60

    const float* aptr = A + (size_t)(bm + arow) * p.lda + akq;
    const float* bptr = B + (size_t)bk * p.ldb + bcol + bnn;

    float4 av  = *(const float4*)(aptr);
    float4 bv0 = *(const float4*)(bptr);
    float4 bv1 = *(const float4*)(bptr + 8 * (size_t)p.ldb);

    for (int k0 = 0; k0 < p.K; k0 += 16) {
        Asd[akq + 0][arow] = pack2(av.x, av.x);
        Asd[akq + 1][arow] = pack2(av.y, av.y);
        Asd[akq + 2][arow] = pack2(av.z, av.z);
        Asd[akq + 3][arow] = pack2(av.w, av.w);
        Bsd[bk][bnn >> 1]       = pack2(bv0.x, bv0.y);
        Bsd[bk][(bnn >> 1) + 1] = pack2(bv0.z, bv0.w);
        Bsd[bk + 8][bnn >> 1]       = pack2(bv1.x, bv1.y);
        Bsd[bk + 8][(bnn >> 1) + 1] = pack2(bv1.z, bv1.w);
        __syncthreads();

        if (k0 + 16 < p.K) {
            av  = *(const float4*)(aptr + k0 + 16);
            bv0 = *(const float4*)(bptr + (size_t)(k0 + 16) * p.ldb);
            bv1 = *(const float4*)(bptr + (size_t)(k0 + 24) * p.ldb);
        }
#pragma unroll
        for (int kk = 0; kk < 16; kk++) {
            ulonglong2 a01 = *(const ulonglong2*)&Asd[kk][ty * 4];
            ulonglong2 a23 = *(const ulonglong2*)&Asd[kk][ty * 4 + 2];
            ulonglong2 bq  = *(const ulonglong2*)&Bsd[kk][tx * 2];
            fma2(acc[0][0], a01.x, bq.x); fma2(acc[0][1], a01.x, bq.y);
            fma2(acc[1][0], a01.y, bq.x); fma2(acc[1][1], a01.y, bq.y);
            fma2(acc[2][0], a23.x, bq.x); fma2(acc[2][1], a23.x, bq.y);
            fma2(acc[3][0], a23.y, bq.x); fma2(acc[3][1], a23.y, bq.y);
        }
        __syncthreads();
    }

    float lv[4][4];
#pragma unroll
    for (int i = 0; i < 4; i++) {
        int row = bm + ty * 4 + i;
        float2 p0 = unpack2(acc[i][0]);
        float2 p1 = unpack2(acc[i][1]);
        float vv[4] = {p0.x, p0.y, p1.x, p1.y};
#pragma unroll
        for (int j = 0; j < 4; j++) {
            int cl = bcol + tx * 4 + j;
            float v = vv[j];
            if (bias) v += bias[cl];
            if (second && p.extra2) v += p.extra2[(size_t)row * p.ld_extra + cl];
            if (p.act == 1) v = (v > 0.0f) ? v : expm1f(v);
            lv[i][j] = v;
            p.C[(size_t)row * (size_t)p.ldc + bn + tx * 4 + j] = v;
        }
    }

    // fused sampler over post-logit 32-col groups (verbatim R4 semantics)
    if (p.sample && second) {
        int lane = tid & 31;
        int pc0 = (bn - p.nsplit) + tx * 4;
        int sg = pc0 >> 5;
        int cb = pc0 & 31;
        uint2 key = g_keys[p.t];
#pragma unroll
        for (int i = 0; i < 4; i++) {
            int row = bm + ty * 4 + i;
            float best = -__int_as_float(0x7f800000);
            int bidx = 0;
            uint32_t ebase = (uint32_t)row * 1024u + (uint32_t)sg * 32u + (uint32_t)cb;
#pragma unroll
            for (int j = 0; j < 4; j++) {
                float val = lv[i][j] + gumbel_of(key, ebase + (uint32_t)j);
                if (val > best) { best = val; bidx = cb + j; }
            }
#pragma unroll
            for (int off = 4; off > 0; off >>= 1) {
                float ov = __shfl_down_sync(0xffffffffu, best, off, 8);
                int   oi = __shfl_down_sync(0xffffffffu, bidx, off, 8);
                if (ov > best || (ov == best && oi < bidx)) { best = ov; bidx = oi; }
            }
            int win = __shfl_sync(0xffffffffu, bidx, 0, 8);
#pragma unroll
            for (int j = 0; j < 4; j++)
                p.stoch[(size_t)row * (size_t)p.ld_st + sg * 32 + cb + j] =
                    (cb + j == win) ? 1.0f : 0.0f;
            if ((lane & 7) == 0) g_idx[row * 32 + sg] = win;
        }
    }
}

// ---------------- gather-sum gi + GRU pointwise (verbatim R2, measured 7.6us) ----------------
__global__ void gru_kernel(const float* __restrict__ w_ih,
                           const float* __restrict__ b_ih,
                           const float* __restrict__ actions,
                           float* __restrict__ out, int t) {
    int b = blockIdx.y;
    int d = blockIdx.x * 256 + threadIdx.x;
    __shared__ int   sidx[32];
    __shared__ float sact[ACTQ];
    if (threadIdx.x < 32) sidx[threadIdx.x] = g_idx[b * 32 + threadIdx.x];
    if (threadIdx.x < ACTQ)
        sact[threadIdx.x] = actions[((size_t)b * TQ + t) * ACTQ + threadIdx.x];
    __syncthreads();

    float gr = b_ih[d], gz = b_ih[DETERQ + d], gn = b_ih[2 * DETERQ + d];
    if (t > 0) {
#pragma unroll 4
        for (int s = 0; s < 32; s++) {
            const float* wr = w_ih + (size_t)(s * 32 + sidx[s]) * (3 * DETERQ);
            gr += wr[d]; gz += wr[DETERQ + d]; gn += wr[2 * DETERQ + d];
        }
    }
#pragma unroll
    for (int j = 0; j < ACTQ; j++) {
        const float* wr = w_ih + (size_t)(TOTQ + j) * (3 * DETERQ);
        float a = sact[j];
        gr += a * wr[d]; gz += a * wr[DETERQ + d]; gn += a * wr[2 * DETERQ + d];
    }
    float hr = g_gh[b * 3 * DETERQ + d];
    float hz = g_gh[b * 3 * DETERQ + DETERQ + d];
    float hn = g_gh[b * 3 * DETERQ + 2 * DETERQ + d];
    float r = 1.0f / (1.0f + expf(-(gr + hr)));
    float z = 1.0f / (1.0f + expf(-(gz + hz)));
    float n = tanhf(gn + r * hn);
    float dprev = g_deter[b * DETERQ + d];
    float dn = (1.0f - z) * n + z * dprev;
    g_deter[b * DETERQ + d] = dn;
    out[((size_t)b * TQ + t) * FEATQ + d] = dn;
}

// ---------------- host launcher ----------------
extern "C" void kernel_launch(void* const* d_in, const int* in_sizes, int n_in,
                              void* d_out, int out_size) {
    (void)in_sizes; (void)n_in; (void)out_size;
    const float* obs      = (const float*)d_in[0];
    const float* actions  = (const float*)d_in[1];
    const float* w_ih     = (const float*)d_in[2];
    const float* w_hh     = (const float*)d_in[3];
    const float* b_ih     = (const float*)d_in[4];
    const float* b_hh     = (const float*)d_in[5];
    const float* prior_w1 = (const float*)d_in[6];
    const float* prior_b1 = (const float*)d_in[7];
    const float* prior_w2 = (const float*)d_in[8];
    const float* prior_b2 = (const float*)d_in[9];
    const float* post_w1  = (const float*)d_in[10];
    const float* post_b1  = (const float*)d_in[11];
    const float* post_w2  = (const float*)d_in[12];
    const float* post_b2  = (const float*)d_in[13];
    float* out = (float*)d_out;

    void *p_po, *p_gh, *p_h, *p_deter;
    cudaGetSymbolAddress(&p_po, g_post_obs);
    cudaGetSymbolAddress(&p_gh, g_gh);
    cudaGetSymbolAddress(&p_h, g_h);
    cudaGetSymbolAddress(&p_deter, g_deter);
    float* post_obs = (float*)p_po;
    float* gh    = (float*)p_gh;
    float* h     = (float*)p_h;
    float* deter = (float*)p_deter;

    init_kernel<<<512, 256>>>();

    obs_gemm_kernel<<<dim3(4, (BQ * TQ) / 128), 256>>>(
        obs, post_w1 + (size_t)DETERQ * HIDQ, post_obs);

    for (int t = 0; t < TQ; t++) {
        // gh = deter @ w_hh + b_hh
        {
            GemmP p;
            p.A = deter; p.lda = DETERQ; p.acol2 = 0;
            p.B1 = w_hh; p.B2 = nullptr; p.ldb = 3 * DETERQ;
            p.bias1 = b_hh; p.bias2 = nullptr;
            p.extra2 = nullptr; p.ld_extra = 0;
            p.C = gh; p.ldc = 3 * DETERQ;
            p.K = DETERQ; p.nsplit = 1 << 30; p.act = 0;
            p.sample = 0; p.t = t; p.stoch = nullptr; p.ld_st = 0;
            gemm_kernel<<<dim3((3 * DETERQ) / 64, BQ / 32), 128>>>(p);
        }
        // gi gather + GRU pointwise -> deter, out[:,t,0:512]
        gru_kernel<<<dim3(DETERQ / 256, BQ), 256>>>(w_ih, b_ih, actions, out, t);

        // h = [ elu(deter@prior_w1 + b1) | elu(deter@post_w1[:512] + post_obs + b1) ]
        {
            GemmP p;
            p.A = deter; p.lda = DETERQ; p.acol2 = 0;
            p.B1 = prior_w1; p.B2 = post_w1; p.ldb = HIDQ;
            p.bias1 = prior_b1; p.bias2 = post_b1;
            p.extra2 = post_obs + (size_t)t * HIDQ; p.ld_extra = (long long)TQ * HIDQ;
            p.C = h; p.ldc = 2 * HIDQ;
            p.K = DETERQ; p.nsplit = HIDQ; p.act = 1;
            p.sample = 0; p.t = t; p.stoch = nullptr; p.ld_st = 0;
            gemm_kernel<<<dim3((2 * HIDQ) / 64, BQ / 32), 128>>>(p);
        }
        // [prior_logits | post_logits] + fused sampler
        {
            GemmP p;
            p.A = h; p.lda = 2 * HIDQ; p.acol2 = HIDQ;
            p.B1 = prior_w2; p.B2 = post_w2; p.ldb = TOTQ;
            p.bias1 = prior_b2; p.bias2 = post_b2;
            p.extra2 = nullptr; p.ld_extra = 0;
            p.C = out + (size_t)t * FEATQ + 1536; p.ldc = (long long)TQ * FEATQ;
            p.K = HIDQ; p.nsplit = TOTQ; p.act = 0;
            p.sample = 1; p.t = t;
            p.stoch = out + (size_t)t * FEATQ + 512; p.ld_st = (long long)TQ * FEATQ;
            gemm_kernel<<<dim3((2 * TOTQ) / 64, BQ / 32), 128>>>(p);
        }
    }
}

// round 13
// speedup vs baseline: 1.1225x; 1.1006x over previous
#include <cuda_runtime.h>
#include <stdint.h>
#include <math.h>

#define BQ 256
#define TQ 128
#define DETERQ 512
#define HIDQ 512
#define TOTQ 1024
#define OBSQ 768
#define ACTQ 7
#define FEATQ 3584

// ---------------- device scratch ----------------
__device__ float g_post_obs[(size_t)BQ * TQ * HIDQ];
__device__ float g_gh[BQ * 3 * DETERQ];
__device__ float g_h[BQ * 2 * HIDQ];
__device__ float g_deter[BQ * DETERQ];
__device__ int   g_idx[BQ * 32];
__device__ uint2 g_keys[TQ];

// ---------------- threefry2x32 (JAX-exact) ----------------
__device__ __forceinline__ uint32_t rotl32(uint32_t x, int d) {
    return (x << d) | (x >> (32 - d));
}
__device__ __forceinline__ void tf4(uint32_t& x0, uint32_t& x1,
                                    int r0, int r1, int r2, int r3) {
    x0 += x1; x1 = rotl32(x1, r0); x1 ^= x0;
    x0 += x1; x1 = rotl32(x1, r1); x1 ^= x0;
    x0 += x1; x1 = rotl32(x1, r2); x1 ^= x0;
    x0 += x1; x1 = rotl32(x1, r3); x1 ^= x0;
}
__device__ __forceinline__ void threefry2x32(uint32_t k0, uint32_t k1,
                                             uint32_t c0, uint32_t c1,
                                             uint32_t& o0, uint32_t& o1) {
    uint32_t ks2 = k0 ^ k1 ^ 0x1BD11BDAu;
    uint32_t x0 = c0 + k0, x1 = c1 + k1;
    tf4(x0, x1, 13, 15, 26, 6);  x0 += k1;  x1 += ks2 + 1u;
    tf4(x0, x1, 17, 29, 16, 24); x0 += ks2; x1 += k0 + 2u;
    tf4(x0, x1, 13, 15, 26, 6);  x0 += k0;  x1 += k1 + 3u;
    tf4(x0, x1, 17, 29, 16, 24); x0 += k1;  x1 += ks2 + 4u;
    tf4(x0, x1, 13, 15, 26, 6);  x0 += ks2; x1 += k0 + 5u;
    o0 = x0; o1 = x1;
}
__device__ __forceinline__ float gumbel_of(uint2 key, uint32_t e) {
    uint32_t o0, o1;
    threefry2x32(key.x, key.y, 0u, e, o0, o1);
    uint32_t bits = o0 ^ o1;
    float f = __uint_as_float((bits >> 9) | 0x3f800000u) - 1.0f;
    float u = fmaxf(1.17549435e-38f, f);
    return -logf(-logf(u));
}

// ---------------- init ----------------
__global__ void init_kernel() {
    int i = blockIdx.x * 256 + threadIdx.x;
    if (i < BQ * DETERQ) g_deter[i] = 0.0f;
    if (blockIdx.x == 0 && threadIdx.x < TQ) {
        uint32_t t = threadIdx.x, o0, o1;
        threefry2x32(0u, 42u, 0u, t, o0, o1);
        g_keys[t] = make_uint2(o0, o1);
    }
}

// ---------------- hoisted obs GEMM (proven bit-exact, unchanged) ----------------
__global__ __launch_bounds__(256) void obs_gemm_kernel(const float* __restrict__ A,
                                                       const float* __restrict__ B,
                                                       float* __restrict__ C) {
    __shared__ __align__(16) float As[2][8][132];
    __shared__ __align__(16) float Bs[2][8][128];
    int bm = blockIdx.y * 128, bn = blockIdx.x * 128;
    int tid = threadIdx.x, tx = tid & 15, ty = tid >> 4;
    int arow = tid >> 1, ak = (tid & 1) * 4;
    int bk = tid >> 5, bn4 = (tid & 31) * 4;
    const float* aptr = A + (size_t)(bm + arow) * OBSQ + ak;
    const float* bptr = B + (size_t)bk * 512 + bn + bn4;
    float acc[8][8];
#pragma unroll
    for (int i = 0; i < 8; i++)
#pragma unroll
        for (int j = 0; j < 8; j++) acc[i][j] = 0.0f;
    float4 av = *(const float4*)aptr;
    float4 bv = *(const float4*)bptr;
    As[0][ak + 0][arow] = av.x; As[0][ak + 1][arow] = av.y;
    As[0][ak + 2][arow] = av.z; As[0][ak + 3][arow] = av.w;
    *(float4*)&Bs[0][bk][bn4] = bv;
    __syncthreads();
    const int NT = OBSQ / 8;
    for (int kt = 0; kt < NT; kt++) {
        int cur = kt & 1;
        if (kt + 1 < NT) {
            av = *(const float4*)(aptr + (kt + 1) * 8);
            bv = *(const float4*)(bptr + (size_t)(kt + 1) * 8 * 512);
        }
#pragma unroll
        for (int kk = 0; kk < 8; kk++) {
            float4 a0 = *(const float4*)&As[cur][kk][ty * 8];
            float4 a1 = *(const float4*)&As[cur][kk][ty * 8 + 4];
            float4 b0 = *(const float4*)&Bs[cur][kk][tx * 8];
            float4 b1 = *(const float4*)&Bs[cur][kk][tx * 8 + 4];
            float a[8] = {a0.x, a0.y, a0.z, a0.w, a1.x, a1.y, a1.z, a1.w};
            float b[8] = {b0.x, b0.y, b0.z, b0.w, b1.x, b1.y, b1.z, b1.w};
#pragma unroll
            for (int i = 0; i < 8; i++)
#pragma unroll
                for (int j = 0; j < 8; j++) acc[i][j] += a[i] * b[j];
        }
        if (kt + 1 < NT) {
            int nxt = cur ^ 1;
            As[nxt][ak + 0][arow] = av.x; As[nxt][ak + 1][arow] = av.y;
            As[nxt][ak + 2][arow] = av.z; As[nxt][ak + 3][arow] = av.w;
            *(float4*)&Bs[nxt][bk][bn4] = bv;
            __syncthreads();
        }
    }
#pragma unroll
    for (int i = 0; i < 8; i++) {
        size_t row = (size_t)(bm + ty * 8 + i);
        *(float4*)(C + row * 512 + bn + tx * 8) =
            make_float4(acc[i][0], acc[i][1], acc[i][2], acc[i][3]);
        *(float4*)(C + row * 512 + bn + tx * 8 + 4) =
            make_float4(acc[i][4], acc[i][5], acc[i][6], acc[i][7]);
    }
}

// ---------------- generic GEMM: 32x64 tile / 256 threads / 2x4 microtile / dbuf ----------
// Per-output accumulation: scalar fp32 FMA, ascending K -> bit-identical to R2 lineage.
struct GemmP {
    const float* A; int lda; int acol2;
    const float* B1; const float* B2; int ldb;
    const float* bias1; const float* bias2;
    const float* extra2; long long ld_extra;
    float* C; long long ldc;
    int K, nsplit;
    int act;       // 0 none, 1 ELU
    int sample;    // gumbel argmax on second half
    int t;
    float* stoch; long long ld_st;
};

__global__ __launch_bounds__(256) void gemm_kernel(GemmP p) {
    __shared__ __align__(16) float As[2][16][36];
    __shared__ __align__(16) float Bs[2][16][64];
    int bn = blockIdx.x * 64;
    int bm = blockIdx.y * 32;
    bool second = (bn >= p.nsplit);
    const float* B    = second ? p.B2 : p.B1;
    const float* bias = second ? p.bias2 : p.bias1;
    const float* A    = p.A + (second ? p.acol2 : 0);
    int bcol = second ? (bn - p.nsplit) : bn;

    int tid = threadIdx.x;
    int tx = tid & 15, ty = tid >> 4;          // ty 0..15 -> rows ty*2+{0,1}

    float acc[2][4];
#pragma unroll
    for (int i = 0; i < 2; i++)
#pragma unroll
        for (int j = 0; j < 4; j++) acc[i][j] = 0.0f;

    int arow = tid >> 3, ak = (tid & 7) * 2;   // A: 32 rows x 16 k, float2 each
    int bk = tid >> 4, bnn = (tid & 15) * 4;   // B: 16 k x 64 n, float4 each

    const float* aptr = A + (size_t)(bm + arow) * p.lda + ak;
    const float* bptr = B + (size_t)bk * p.ldb + bcol + bnn;

    float2 av = *(const float2*)aptr;
    float4 bv = *(const float4*)bptr;
    As[0][ak][arow] = av.x; As[0][ak + 1][arow] = av.y;
    *(float4*)&Bs[0][bk][bnn] = bv;
    __syncthreads();

    int NT = p.K / 16;
    for (int kt = 0; kt < NT; kt++) {
        int cur = kt & 1;
        if (kt + 1 < NT) {
            av = *(const float2*)(aptr + (kt + 1) * 16);
            bv = *(const float4*)(bptr + (size_t)((kt + 1) * 16) * p.ldb);
        }
#pragma unroll
        for (int kk = 0; kk < 16; kk++) {
            float2 a2 = *(const float2*)&As[cur][kk][ty * 2];
            float4 b4 = *(const float4*)&Bs[cur][kk][tx * 4];
            acc[0][0] += a2.x * b4.x; acc[0][1] += a2.x * b4.y;
            acc[0][2] += a2.x * b4.z; acc[0][3] += a2.x * b4.w;
            acc[1][0] += a2.y * b4.x; acc[1][1] += a2.y * b4.y;
            acc[1][2] += a2.y * b4.z; acc[1][3] += a2.y * b4.w;
        }
        if (kt + 1 < NT) {
            int nxt = cur ^ 1;
            As[nxt][ak][arow] = av.x; As[nxt][ak + 1][arow] = av.y;
            *(float4*)&Bs[nxt][bk][bnn] = bv;
            __syncthreads();
        }
    }

    float lv[2][4];
#pragma unroll
    for (int i = 0; i < 2; i++) {
        int row = bm + ty * 2 + i;
#pragma unroll
        for (int j = 0; j < 4; j++) {
            int cl = bcol + tx * 4 + j;
            float v = acc[i][j];
            if (bias) v += bias[cl];
            if (second && p.extra2) v += p.extra2[(size_t)row * p.ld_extra + cl];
            if (p.act == 1) v = (v > 0.0f) ? v : expm1f(v);
            lv[i][j] = v;
        }
        *(float4*)(p.C + (size_t)row * (size_t)p.ldc + bn + tx * 4) =
            make_float4(lv[i][0], lv[i][1], lv[i][2], lv[i][3]);
    }

    // fused sampler over post-logit 32-col groups (verbatim proven semantics)
    if (p.sample && second) {
        int lane = tid & 31;
        int pc0 = (bn - p.nsplit) + tx * 4;   // post-relative col of j=0
        int sg = pc0 >> 5;
        int cb = pc0 & 31;
        uint2 key = g_keys[p.t];
#pragma unroll
        for (int i = 0; i < 2; i++) {
            int row = bm + ty * 2 + i;
            float best = -__int_as_float(0x7f800000);
            int bidx = 0;
            uint32_t ebase = (uint32_t)row * 1024u + (uint32_t)sg * 32u + (uint32_t)cb;
#pragma unroll
            for (int j = 0; j < 4; j++) {
                float val = lv[i][j] + gumbel_of(key, ebase + (uint32_t)j);
                if (val > best) { best = val; bidx = cb + j; }
            }
#pragma unroll
            for (int off = 4; off > 0; off >>= 1) {
                float ov = __shfl_down_sync(0xffffffffu, best, off, 8);
                int   oi = __shfl_down_sync(0xffffffffu, bidx, off, 8);
                if (ov > best || (ov == best && oi < bidx)) { best = ov; bidx = oi; }
            }
            int win = __shfl_sync(0xffffffffu, bidx, 0, 8);
            *(float4*)(p.stoch + (size_t)row * (size_t)p.ld_st + sg * 32 + cb) =
                make_float4((cb + 0 == win) ? 1.0f : 0.0f,
                            (cb + 1 == win) ? 1.0f : 0.0f,
                            (cb + 2 == win) ? 1.0f : 0.0f,
                            (cb + 3 == win) ? 1.0f : 0.0f);
            if ((lane & 7) == 0) g_idx[row * 32 + sg] = win;
        }
    }
}

// ---------------- gather-sum gi + GRU pointwise (verbatim R2) ----------------
__global__ void gru_kernel(const float* __restrict__ w_ih,
                           const float* __restrict__ b_ih,
                           const float* __restrict__ actions,
                           float* __restrict__ out, int t) {
    int b = blockIdx.y;
    int d = blockIdx.x * 256 + threadIdx.x;
    __shared__ int   sidx[32];
    __shared__ float sact[ACTQ];
    if (threadIdx.x < 32) sidx[threadIdx.x] = g_idx[b * 32 + threadIdx.x];
    if (threadIdx.x < ACTQ)
        sact[threadIdx.x] = actions[((size_t)b * TQ + t) * ACTQ + threadIdx.x];
    __syncthreads();

    float gr = b_ih[d], gz = b_ih[DETERQ + d], gn = b_ih[2 * DETERQ + d];
    if (t > 0) {
#pragma unroll 4
        for (int s = 0; s < 32; s++) {
            const float* wr = w_ih + (size_t)(s * 32 + sidx[s]) * (3 * DETERQ);
            gr += wr[d]; gz += wr[DETERQ + d]; gn += wr[2 * DETERQ + d];
        }
    }
#pragma unroll
    for (int j = 0; j < ACTQ; j++) {
        const float* wr = w_ih + (size_t)(TOTQ + j) * (3 * DETERQ);
        float a = sact[j];
        gr += a * wr[d]; gz += a * wr[DETERQ + d]; gn += a * wr[2 * DETERQ + d];
    }
    float hr = g_gh[b * 3 * DETERQ + d];
    float hz = g_gh[b * 3 * DETERQ + DETERQ + d];
    float hn = g_gh[b * 3 * DETERQ + 2 * DETERQ + d];
    float r = 1.0f / (1.0f + expf(-(gr + hr)));
    float z = 1.0f / (1.0f + expf(-(gz + hz)));
    float n = tanhf(gn + r * hn);
    float dprev = g_deter[b * DETERQ + d];
    float dn = (1.0f - z) * n + z * dprev;
    g_deter[b * DETERQ + d] = dn;
    out[((size_t)b * TQ + t) * FEATQ + d] = dn;
}

// ---------------- host launcher ----------------
extern "C" void kernel_launch(void* const* d_in, const int* in_sizes, int n_in,
                              void* d_out, int out_size) {
    (void)in_sizes; (void)n_in; (void)out_size;
    const float* obs      = (const float*)d_in[0];
    const float* actions  = (const float*)d_in[1];
    const float* w_ih     = (const float*)d_in[2];
    const float* w_hh     = (const float*)d_in[3];
    const float* b_ih     = (const float*)d_in[4];
    const float* b_hh     = (const float*)d_in[5];
    const float* prior_w1 = (const float*)d_in[6];
    const float* prior_b1 = (const float*)d_in[7];
    const float* prior_w2 = (const float*)d_in[8];
    const float* prior_b2 = (const float*)d_in[9];
    const float* post_w1  = (const float*)d_in[10];
    const float* post_b1  = (const float*)d_in[11];
    const float* post_w2  = (const float*)d_in[12];
    const float* post_b2  = (const float*)d_in[13];
    float* out = (float*)d_out;

    void *p_po, *p_gh, *p_h, *p_deter;
    cudaGetSymbolAddress(&p_po, g_post_obs);
    cudaGetSymbolAddress(&p_gh, g_gh);
    cudaGetSymbolAddress(&p_h, g_h);
    cudaGetSymbolAddress(&p_deter, g_deter);
    float* post_obs = (float*)p_po;
    float* gh    = (float*)p_gh;
    float* h     = (float*)p_h;
    float* deter = (float*)p_deter;

    init_kernel<<<512, 256>>>();

    obs_gemm_kernel<<<dim3(4, (BQ * TQ) / 128), 256>>>(
        obs, post_w1 + (size_t)DETERQ * HIDQ, post_obs);

    for (int t = 0; t < TQ; t++) {
        // gh = deter @ w_hh + b_hh
        {
            GemmP p;
            p.A = deter; p.lda = DETERQ; p.acol2 = 0;
            p.B1 = w_hh; p.B2 = nullptr; p.ldb = 3 * DETERQ;
            p.bias1 = b_hh; p.bias2 = nullptr;
            p.extra2 = nullptr; p.ld_extra = 0;
            p.C = gh; p.ldc = 3 * DETERQ;
            p.K = DETERQ; p.nsplit = 1 << 30; p.act = 0;
            p.sample = 0; p.t = t; p.stoch = nullptr; p.ld_st = 0;
            gemm_kernel<<<dim3((3 * DETERQ) / 64, BQ / 32), 256>>>(p);
        }
        // gi gather + GRU pointwise -> deter, out[:,t,0:512]
        gru_kernel<<<dim3(DETERQ / 256, BQ), 256>>>(w_ih, b_ih, actions, out, t);

        // h = [ elu(deter@prior_w1 + b1) | elu(deter@post_w1[:512] + post_obs + b1) ]
        {
            GemmP p;
            p.A = deter; p.lda = DETERQ; p.acol2 = 0;
            p.B1 = prior_w1; p.B2 = post_w1; p.ldb = HIDQ;
            p.bias1 = prior_b1; p.bias2 = post_b1;
            p.extra2 = post_obs + (size_t)t * HIDQ; p.ld_extra = (long long)TQ * HIDQ;
            p.C = h; p.ldc = 2 * HIDQ;
            p.K = DETERQ; p.nsplit = HIDQ; p.act = 1;
            p.sample = 0; p.t = t; p.stoch = nullptr; p.ld_st = 0;
            gemm_kernel<<<dim3((2 * HIDQ) / 64, BQ / 32), 256>>>(p);
        }
        // [prior_logits | post_logits] + fused sampler -> out, stoch, g_idx
        {
            GemmP p;
            p.A = h; p.lda = 2 * HIDQ; p.acol2 = HIDQ;
            p.B1 = prior_w2; p.B2 = post_w2; p.ldb = TOTQ;
            p.bias1 = prior_b2; p.bias2 = post_b2;
            p.extra2 = nullptr; p.ld_extra = 0;
            p.C = out + (size_t)t * FEATQ + 1536; p.ldc = (long long)TQ * FEATQ;
            p.K = HIDQ; p.nsplit = TOTQ; p.act = 0;
            p.sample = 1; p.t = t;
            p.stoch = out + (size_t)t * FEATQ + 512; p.ld_st = (long long)TQ * FEATQ;
            gemm_kernel<<<dim3((2 * TOTQ) / 64, BQ / 32), 256>>>(p);
        }
    }
}

// round 14
// speedup vs baseline: 1.4041x; 1.2509x over previous
#include <cuda_runtime.h>
#include <stdint.h>
#include <math.h>

#define BQ 256
#define TQ 128
#define DETERQ 512
#define HIDQ 512
#define TOTQ 1024
#define OBSQ 768
#define ACTQ 7
#define FEATQ 3584

// ---------------- device scratch ----------------
__device__ float g_post_obs[(size_t)BQ * TQ * HIDQ];
__device__ float g_gh[BQ * 3 * DETERQ];
__device__ float g_h[BQ * 2 * HIDQ];           // row: [prior 0:512 | post 512:1024]
__device__ float g_deter[2][BQ * DETERQ];      // ping-pong
__device__ int   g_idx[BQ * 32];
__device__ uint2 g_keys[TQ];

// ---------------- threefry2x32 (JAX-exact) ----------------
__device__ __forceinline__ uint32_t rotl32(uint32_t x, int d) {
    return (x << d) | (x >> (32 - d));
}
__device__ __forceinline__ void tf4(uint32_t& x0, uint32_t& x1,
                                    int r0, int r1, int r2, int r3) {
    x0 += x1; x1 = rotl32(x1, r0); x1 ^= x0;
    x0 += x1; x1 = rotl32(x1, r1); x1 ^= x0;
    x0 += x1; x1 = rotl32(x1, r2); x1 ^= x0;
    x0 += x1; x1 = rotl32(x1, r3); x1 ^= x0;
}
__device__ __forceinline__ void threefry2x32(uint32_t k0, uint32_t k1,
                                             uint32_t c0, uint32_t c1,
                                             uint32_t& o0, uint32_t& o1) {
    uint32_t ks2 = k0 ^ k1 ^ 0x1BD11BDAu;
    uint32_t x0 = c0 + k0, x1 = c1 + k1;
    tf4(x0, x1, 13, 15, 26, 6);  x0 += k1;  x1 += ks2 + 1u;
    tf4(x0, x1, 17, 29, 16, 24); x0 += ks2; x1 += k0 + 2u;
    tf4(x0, x1, 13, 15, 26, 6);  x0 += k0;  x1 += k1 + 3u;
    tf4(x0, x1, 17, 29, 16, 24); x0 += k1;  x1 += ks2 + 4u;
    tf4(x0, x1, 13, 15, 26, 6);  x0 += ks2; x1 += k0 + 5u;
    o0 = x0; o1 = x1;
}
__device__ __forceinline__ float gumbel_of(uint2 key, uint32_t e) {
    uint32_t o0, o1;
    threefry2x32(key.x, key.y, 0u, e, o0, o1);
    uint32_t bits = o0 ^ o1;
    float f = __uint_as_float((bits >> 9) | 0x3f800000u) - 1.0f;
    float u = fmaxf(1.17549435e-38f, f);
    return -logf(-logf(u));
}

// ---------------- init ----------------
__global__ void init_kernel() {
    int i = blockIdx.x * 256 + threadIdx.x;
    if (i < BQ * DETERQ) g_deter[0][i] = 0.0f;
    if (blockIdx.x == 0 && threadIdx.x < TQ) {
        uint32_t t = threadIdx.x, o0, o1;
        threefry2x32(0u, 42u, 0u, t, o0, o1);
        g_keys[t] = make_uint2(o0, o1);
    }
}

// ---------------- hoisted obs GEMM (proven bit-exact, unchanged) ----------------
__global__ __launch_bounds__(256) void obs_gemm_kernel(const float* __restrict__ A,
                                                       const float* __restrict__ B,
                                                       float* __restrict__ C) {
    __shared__ __align__(16) float As[2][8][132];
    __shared__ __align__(16) float Bs[2][8][128];
    int bm = blockIdx.y * 128, bn = blockIdx.x * 128;
    int tid = threadIdx.x, tx = tid & 15, ty = tid >> 4;
    int arow = tid >> 1, ak = (tid & 1) * 4;
    int bk = tid >> 5, bn4 = (tid & 31) * 4;
    const float* aptr = A + (size_t)(bm + arow) * OBSQ + ak;
    const float* bptr = B + (size_t)bk * 512 + bn + bn4;
    float acc[8][8];
#pragma unroll
    for (int i = 0; i < 8; i++)
#pragma unroll
        for (int j = 0; j < 8; j++) acc[i][j] = 0.0f;
    float4 av = *(const float4*)aptr;
    float4 bv = *(const float4*)bptr;
    As[0][ak + 0][arow] = av.x; As[0][ak + 1][arow] = av.y;
    As[0][ak + 2][arow] = av.z; As[0][ak + 3][arow] = av.w;
    *(float4*)&Bs[0][bk][bn4] = bv;
    __syncthreads();
    const int NT = OBSQ / 8;
    for (int kt = 0; kt < NT; kt++) {
        int cur = kt & 1;
        if (kt + 1 < NT) {
            av = *(const float4*)(aptr + (kt + 1) * 8);
            bv = *(const float4*)(bptr + (size_t)(kt + 1) * 8 * 512);
        }
#pragma unroll
        for (int kk = 0; kk < 8; kk++) {
            float4 a0 = *(const float4*)&As[cur][kk][ty * 8];
            float4 a1 = *(const float4*)&As[cur][kk][ty * 8 + 4];
            float4 b0 = *(const float4*)&Bs[cur][kk][tx * 8];
            float4 b1 = *(const float4*)&Bs[cur][kk][tx * 8 + 4];
            float a[8] = {a0.x, a0.y, a0.z, a0.w, a1.x, a1.y, a1.z, a1.w};
            float b[8] = {b0.x, b0.y, b0.z, b0.w, b1.x, b1.y, b1.z, b1.w};
#pragma unroll
            for (int i = 0; i < 8; i++)
#pragma unroll
                for (int j = 0; j < 8; j++) acc[i][j] += a[i] * b[j];
        }
        if (kt + 1 < NT) {
            int nxt = cur ^ 1;
            As[nxt][ak + 0][arow] = av.x; As[nxt][ak + 1][arow] = av.y;
            As[nxt][ak + 2][arow] = av.z; As[nxt][ak + 3][arow] = av.w;
            *(float4*)&Bs[nxt][bk][bn4] = bv;
            __syncthreads();
        }
    }
#pragma unroll
    for (int i = 0; i < 8; i++) {
        size_t row = (size_t)(bm + ty * 8 + i);
        *(float4*)(C + row * 512 + bn + tx * 8) =
            make_float4(acc[i][0], acc[i][1], acc[i][2], acc[i][3]);
        *(float4*)(C + row * 512 + bn + tx * 8 + 4) =
            make_float4(acc[i][4], acc[i][5], acc[i][6], acc[i][7]);
    }
}

// ---------------- generic GEMM: 32x64 tile / 256 thr / 2x4 microtile / dbuf ----------
// Scalar fp32 FMA ascending K -> bit-identical to R2/R13 lineage.
struct GemmP {
    const float* A; int lda;
    const float* B; int ldb;
    const float* bias;
    const float* extra; long long ld_extra;
    float* C; long long ldc;
    int K;
    int act;       // 0 none, 1 ELU
    int sample;    // gumbel argmax (C is post-logits base, N=1024)
    int t;
    float* stoch; long long ld_st;
};

__global__ __launch_bounds__(256) void gemm_kernel(GemmP p) {
    __shared__ __align__(16) float As[2][16][36];
    __shared__ __align__(16) float Bs[2][16][64];
    int bn = blockIdx.x * 64;
    int bm = blockIdx.y * 32;

    int tid = threadIdx.x;
    int tx = tid & 15, ty = tid >> 4;

    float acc[2][4];
#pragma unroll
    for (int i = 0; i < 2; i++)
#pragma unroll
        for (int j = 0; j < 4; j++) acc[i][j] = 0.0f;

    int arow = tid >> 3, ak = (tid & 7) * 2;
    int bk = tid >> 4, bnn = (tid & 15) * 4;

    const float* aptr = p.A + (size_t)(bm + arow) * p.lda + ak;
    const float* bptr = p.B + (size_t)bk * p.ldb + bn + bnn;

    float2 av = *(const float2*)aptr;
    float4 bv = *(const float4*)bptr;
    As[0][ak][arow] = av.x; As[0][ak + 1][arow] = av.y;
    *(float4*)&Bs[0][bk][bnn] = bv;
    __syncthreads();

    int NT = p.K / 16;
    for (int kt = 0; kt < NT; kt++) {
        int cur = kt & 1;
        if (kt + 1 < NT) {
            av = *(const float2*)(aptr + (kt + 1) * 16);
            bv = *(const float4*)(bptr + (size_t)((kt + 1) * 16) * p.ldb);
        }
#pragma unroll
        for (int kk = 0; kk < 16; kk++) {
            float2 a2 = *(const float2*)&As[cur][kk][ty * 2];
            float4 b4 = *(const float4*)&Bs[cur][kk][tx * 4];
            acc[0][0] += a2.x * b4.x; acc[0][1] += a2.x * b4.y;
            acc[0][2] += a2.x * b4.z; acc[0][3] += a2.x * b4.w;
            acc[1][0] += a2.y * b4.x; acc[1][1] += a2.y * b4.y;
            acc[1][2] += a2.y * b4.z; acc[1][3] += a2.y * b4.w;
        }
        if (kt + 1 < NT) {
            int nxt = cur ^ 1;
            As[nxt][ak][arow] = av.x; As[nxt][ak + 1][arow] = av.y;
            *(float4*)&Bs[nxt][bk][bnn] = bv;
            __syncthreads();
        }
    }

    float lv[2][4];
#pragma unroll
    for (int i = 0; i < 2; i++) {
        int row = bm + ty * 2 + i;
#pragma unroll
        for (int j = 0; j < 4; j++) {
            int cl = bn + tx * 4 + j;
            float v = acc[i][j];
            if (p.bias) v += p.bias[cl];
            if (p.extra) v += p.extra[(size_t)row * p.ld_extra + cl];
            if (p.act == 1) v = (v > 0.0f) ? v : expm1f(v);
            lv[i][j] = v;
        }
        *(float4*)(p.C + (size_t)row * (size_t)p.ldc + bn + tx * 4) =
            make_float4(lv[i][0], lv[i][1], lv[i][2], lv[i][3]);
    }

    if (p.sample) {
        int lane = tid & 31;
        int pc0 = bn + tx * 4;           // col within post logits
        int sg = pc0 >> 5, cb = pc0 & 31;
        uint2 key = g_keys[p.t];
#pragma unroll
        for (int i = 0; i < 2; i++) {
            int row = bm + ty * 2 + i;
            float best = -__int_as_float(0x7f800000);
            int bidx = 0;
            uint32_t ebase = (uint32_t)row * 1024u + (uint32_t)sg * 32u + (uint32_t)cb;
#pragma unroll
            for (int j = 0; j < 4; j++) {
                float val = lv[i][j] + gumbel_of(key, ebase + (uint32_t)j);
                if (val > best) { best = val; bidx = cb + j; }
            }
#pragma unroll
            for (int off = 4; off > 0; off >>= 1) {
                float ov = __shfl_down_sync(0xffffffffu, best, off, 8);
                int   oi = __shfl_down_sync(0xffffffffu, bidx, off, 8);
                if (ov > best || (ov == best && oi < bidx)) { best = ov; bidx = oi; }
            }
            int win = __shfl_sync(0xffffffffu, bidx, 0, 8);
            *(float4*)(p.stoch + (size_t)row * (size_t)p.ld_st + sg * 32 + cb) =
                make_float4((cb + 0 == win) ? 1.0f : 0.0f,
                            (cb + 1 == win) ? 1.0f : 0.0f,
                            (cb + 2 == win) ? 1.0f : 0.0f,
                            (cb + 3 == win) ? 1.0f : 0.0f);
            if ((lane & 7) == 0) g_idx[row * 32 + sg] = win;
        }
    }
}

// ---------------- gather-sum gi + GRU pointwise (verbatim R2, ping-pong deter) --------
__global__ void gru_kernel(const float* __restrict__ w_ih,
                           const float* __restrict__ b_ih,
                           const float* __restrict__ actions,
                           const float* __restrict__ dprev,
                           float* __restrict__ dnext,
                           float* __restrict__ out, int t) {
    int b = blockIdx.y;
    int d = blockIdx.x * 256 + threadIdx.x;
    __shared__ int   sidx[32];
    __shared__ float sact[ACTQ];
    if (threadIdx.x < 32) sidx[threadIdx.x] = g_idx[b * 32 + threadIdx.x];
    if (threadIdx.x < ACTQ)
        sact[threadIdx.x] = actions[((size_t)b * TQ + t) * ACTQ + threadIdx.x];
    __syncthreads();

    float gr = b_ih[d], gz = b_ih[DETERQ + d], gn = b_ih[2 * DETERQ + d];
    if (t > 0) {
#pragma unroll 4
        for (int s = 0; s < 32; s++) {
            const float* wr = w_ih + (size_t)(s * 32 + sidx[s]) * (3 * DETERQ);
            gr += wr[d]; gz += wr[DETERQ + d]; gn += wr[2 * DETERQ + d];
        }
    }
#pragma unroll
    for (int j = 0; j < ACTQ; j++) {
        const float* wr = w_ih + (size_t)(TOTQ + j) * (3 * DETERQ);
        float a = sact[j];
        gr += a * wr[d]; gz += a * wr[DETERQ + d]; gn += a * wr[2 * DETERQ + d];
    }
    float hr = g_gh[b * 3 * DETERQ + d];
    float hz = g_gh[b * 3 * DETERQ + DETERQ + d];
    float hn = g_gh[b * 3 * DETERQ + 2 * DETERQ + d];
    float r = 1.0f / (1.0f + expf(-(gr + hr)));
    float z = 1.0f / (1.0f + expf(-(gz + hz)));
    float n = tanhf(gn + r * hn);
    float dp = dprev[b * DETERQ + d];
    float dn = (1.0f - z) * n + z * dp;
    dnext[b * DETERQ + d] = dn;
    out[((size_t)b * TQ + t) * FEATQ + d] = dn;
}

// ---------------- host launcher: 3-stream captured DAG ----------------
extern "C" void kernel_launch(void* const* d_in, const int* in_sizes, int n_in,
                              void* d_out, int out_size) {
    (void)in_sizes; (void)n_in; (void)out_size;
    const float* obs      = (const float*)d_in[0];
    const float* actions  = (const float*)d_in[1];
    const float* w_ih     = (const float*)d_in[2];
    const float* w_hh     = (const float*)d_in[3];
    const float* b_ih     = (const float*)d_in[4];
    const float* b_hh     = (const float*)d_in[5];
    const float* prior_w1 = (const float*)d_in[6];
    const float* prior_b1 = (const float*)d_in[7];
    const float* prior_w2 = (const float*)d_in[8];
    const float* prior_b2 = (const float*)d_in[9];
    const float* post_w1  = (const float*)d_in[10];
    const float* post_b1  = (const float*)d_in[11];
    const float* post_w2  = (const float*)d_in[12];
    const float* post_b2  = (const float*)d_in[13];
    float* out = (float*)d_out;

    void *p_po, *p_gh, *p_h, *p_deter;
    cudaGetSymbolAddress(&p_po, g_post_obs);
    cudaGetSymbolAddress(&p_gh, g_gh);
    cudaGetSymbolAddress(&p_h, g_h);
    cudaGetSymbolAddress(&p_deter, g_deter);
    float* post_obs = (float*)p_po;
    float* gh    = (float*)p_gh;
    float* h_all = (float*)p_h;
    float* bufA  = (float*)p_deter;
    float* bufB  = bufA + BQ * DETERQ;

    // streams/events created once, outside any capture (first call is the
    // plain correctness run). No device-memory allocation involved.
    static cudaStream_t s_gh = nullptr, s_pr = nullptr;
    static cudaEvent_t e_init, e_gh, e_gru, e_ph, e_prend;
    if (!s_gh) {
        cudaStreamCreateWithFlags(&s_gh, cudaStreamNonBlocking);
        cudaStreamCreateWithFlags(&s_pr, cudaStreamNonBlocking);
        cudaEventCreateWithFlags(&e_init, cudaEventDisableTiming);
        cudaEventCreateWithFlags(&e_gh, cudaEventDisableTiming);
        cudaEventCreateWithFlags(&e_gru, cudaEventDisableTiming);
        cudaEventCreateWithFlags(&e_ph, cudaEventDisableTiming);
        cudaEventCreateWithFlags(&e_prend, cudaEventDisableTiming);
    }

    init_kernel<<<512, 256>>>();
    obs_gemm_kernel<<<dim3(4, (BQ * TQ) / 128), 256>>>(
        obs, post_w1 + (size_t)DETERQ * HIDQ, post_obs);
    cudaEventRecord(e_init, 0);

    for (int t = 0; t < TQ; t++) {
        float* dprev = (t & 1) ? bufB : bufA;
        float* dnext = (t & 1) ? bufA : bufB;

        // --- gh(t) on s_gh: reads dprev (ready: init or gru(t-1)) ---
        cudaStreamWaitEvent(s_gh, (t == 0) ? e_init : e_gru, 0);
        {
            GemmP p;
            p.A = dprev; p.lda = DETERQ;
            p.B = w_hh; p.ldb = 3 * DETERQ;
            p.bias = b_hh; p.extra = nullptr; p.ld_extra = 0;
            p.C = gh; p.ldc = 3 * DETERQ;
            p.K = DETERQ; p.act = 0; p.sample = 0; p.t = t;
            p.stoch = nullptr; p.ld_st = 0;
            gemm_kernel<<<dim3((3 * DETERQ) / 64, BQ / 32), 256, 0, s_gh>>>(p);
        }
        cudaEventRecord(e_gh, s_gh);

        // --- main chain on stream 0: gru -> h_post -> post_logits+sample ---
        cudaStreamWaitEvent(0, e_gh, 0);
        if (t >= 1) cudaStreamWaitEvent(0, e_ph, 0);   // h_prior(t-1) read of dprev done
        gru_kernel<<<dim3(DETERQ / 256, BQ), 256>>>(w_ih, b_ih, actions,
                                                    dprev, dnext, out, t);
        cudaEventRecord(e_gru, 0);

        // --- prior branch on s_pr: h_prior -> prior_logits (output only) ---
        cudaStreamWaitEvent(s_pr, e_gru, 0);
        {
            GemmP p;
            p.A = dnext; p.lda = DETERQ;
            p.B = prior_w1; p.ldb = HIDQ;
            p.bias = prior_b1; p.extra = nullptr; p.ld_extra = 0;
            p.C = h_all; p.ldc = 2 * HIDQ;
            p.K = DETERQ; p.act = 1; p.sample = 0; p.t = t;
            p.stoch = nullptr; p.ld_st = 0;
            gemm_kernel<<<dim3(HIDQ / 64, BQ / 32), 256, 0, s_pr>>>(p);
        }
        cudaEventRecord(e_ph, s_pr);
        {
            GemmP p;
            p.A = h_all; p.lda = 2 * HIDQ;
            p.B = prior_w2; p.ldb = TOTQ;
            p.bias = prior_b2; p.extra = nullptr; p.ld_extra = 0;
            p.C = out + (size_t)t * FEATQ + 1536; p.ldc = (long long)TQ * FEATQ;
            p.K = HIDQ; p.act = 0; p.sample = 0; p.t = t;
            p.stoch = nullptr; p.ld_st = 0;
            gemm_kernel<<<dim3(TOTQ / 64, BQ / 32), 256, 0, s_pr>>>(p);
        }

        // --- h_post on stream 0 ---
        {
            GemmP p;
            p.A = dnext; p.lda = DETERQ;
            p.B = post_w1; p.ldb = HIDQ;
            p.bias = post_b1;
            p.extra = post_obs + (size_t)t * HIDQ; p.ld_extra = (long long)TQ * HIDQ;
            p.C = h_all + HIDQ; p.ldc = 2 * HIDQ;
            p.K = DETERQ; p.act = 1; p.sample = 0; p.t = t;
            p.stoch = nullptr; p.ld_st = 0;
            gemm_kernel<<<dim3(HIDQ / 64, BQ / 32), 256>>>(p);
        }
        // --- post_logits + fused sampler on stream 0 ---
        {
            GemmP p;
            p.A = h_all + HIDQ; p.lda = 2 * HIDQ;
            p.B = post_w2; p.ldb = TOTQ;
            p.bias = post_b2; p.extra = nullptr; p.ld_extra = 0;
            p.C = out + (size_t)t * FEATQ + 2560; p.ldc = (long long)TQ * FEATQ;
            p.K = HIDQ; p.act = 0; p.sample = 1; p.t = t;
            p.stoch = out + (size_t)t * FEATQ + 512; p.ld_st = (long long)TQ * FEATQ;
            gemm_kernel<<<dim3(TOTQ / 64, BQ / 32), 256>>>(p);
        }
    }

    // join forked streams back into stream 0 before capture ends
    cudaEventRecord(e_prend, s_pr);
    cudaStreamWaitEvent(0, e_prend, 0);
    cudaStreamWaitEvent(0, e_gh, 0);
}